// round 13
// baseline (speedup 1.0000x reference)
#include <cuda_runtime.h>

#define EE 25
#define HH 37
#define NJ 6
#define PEC 27                   // padded cols (f2 per plane row)
#define PHR 40                   // padded rows + guard
#define PLANE2 (PHR * PEC)       // 1080 f2 per plane
#define NF2 (3 * PLANE2)         // 3240 f2 per buffer (3 planes)
#define SBAT2 (2 * NF2)          // f2 per batch (ping+pong)
#define NB 4                     // batches per CTA (one CTA per SM)
#define SMEM_F2 (NB * SBAT2)     // 25920 f2
#define NTH 480
#define NBAND 19
#define NVP (NBAND * EE)         // 475 vertical pairs
#define GAMMA 0.9f
#define ADDC 12
#define MROW (HH * (NJ + 1))     // 259 mask rows per batch

// dr = {0,1,1,0,-1,-1} ; dc = {1,0,-1,-1,0,1}  packed (d+1), 2 bits per k
#define DR_PACK 105u
#define DC_PACK 2310u

#define SMEM_WORDS (2 * SMEM_F2 + NB * MROW)
#define SMEM_BYTES (SMEM_WORDS * 4)

__global__ __launch_bounds__(NTH, 1) void vin_kernel(
    const float* __restrict__ goals,   // [B,6,25,25]
    const int*   __restrict__ state,   // [B,3]
    const float* __restrict__ obst,    // [B,25,25]
    const int*   __restrict__ n_iter,  // [1]
    float* __restrict__ out)           // [B,4]
{
    extern __shared__ float sm[];
    float2* smf2 = (float2*)sm;
    unsigned* obsh = (unsigned*)(sm + 2 * SMEM_F2);  // [NB][37]
    unsigned* gbsh = obsh + NB * HH;                 // [NB][6*37]

    const int b0  = blockIdx.x * NB;
    const int tid = threadIdx.x;

    // zero all float buffers (incl. halos & guard rows)
    for (int i = tid; i < 2 * SMEM_F2; i += NTH) sm[i] = 0.0f;

    // build bitmasks for all batches (tt<37 -> obstacle row, else goal row)
    for (int t = tid; t < NB * MROW; t += NTH) {
        int X  = t / MROW;
        int tt = t - X * MROW;
        int bb = b0 + X;
        int r, j;
        if (tt < HH) { r = tt; j = -1; }
        else         { int t2 = tt - HH; j = t2 / HH; r = t2 - j * HH; }
        unsigned bits = 0u;
        #pragma unroll 1
        for (int c = 0; c < EE; ++c) {
            int u = r + (c >> 1) - ADDC;
            if (u >= 0 && u < EE) {
                if (j < 0) {
                    if (obst[(bb * EE + u) * EE + c] == 0.0f) bits |= (1u << c);
                } else {
                    if (goals[((bb * NJ + j) * EE + u) * EE + c] != 0.0f) bits |= (1u << c);
                }
            }
        }
        if (j < 0) obsh[X * HH + r] = bits;
        else       gbsh[X * NJ * HH + (tt - HH)] = bits;
    }
    __syncthreads();

    const bool active = (tid < NVP);
    int base2 = 0;     // f2 index of cell A within plane 0
    float AmA[NB], AmB[NB];
    unsigned cgA[NB], cgB[NB];
    float2 oA0[NB], oA1[NB], oA2[NB], oB0[NB], oB1[NB], oB2[NB];
    #pragma unroll
    for (int X = 0; X < NB; ++X) {
        AmA[X] = AmB[X] = 0.f; cgA[X] = cgB[X] = 0u;
        oA0[X] = oA1[X] = oA2[X] = make_float2(0.f, 0.f);
        oB0[X] = oB1[X] = oB2[X] = make_float2(0.f, 0.f);
    }

    if (active) {
        int band = tid / EE;
        int c    = tid - band * EE;
        int rA   = 2 * band;
        int rB   = rA + 1;
        base2 = (rA + 1) * PEC + (c + 1);
        int rBc = (rB < HH) ? rB : (HH - 1);

        #pragma unroll
        for (int X = 0; X < NB; ++X) {
            unsigned obA = (obsh[X * HH + rA] >> c) & 1u;
            unsigned obB = (rB < HH) ? ((obsh[X * HH + rB] >> c) & 1u) : 0u;
            AmA[X] = obA ? GAMMA : 0.0f;
            AmB[X] = obB ? GAMMA : 0.0f;
            unsigned gA = 0u, gB = 0u;
            #pragma unroll
            for (int j = 0; j < NJ; ++j) {
                gA |= ((gbsh[X * NJ * HH + j * HH + rA ] >> c) & 1u) << j;
                gB |= ((gbsh[X * NJ * HH + j * HH + rBc] >> c) & 1u) << j;
            }
            cgA[X] = obA ? gA : 0u;
            cgB[X] = obB ? gB : 0u;

            oA0[X] = make_float2((cgA[X] &  1u) ? 1.f : 0.f, (cgA[X] &  8u) ? 1.f : 0.f);
            oA1[X] = make_float2((cgA[X] &  2u) ? 1.f : 0.f, (cgA[X] & 16u) ? 1.f : 0.f);
            oA2[X] = make_float2((cgA[X] &  4u) ? 1.f : 0.f, (cgA[X] & 32u) ? 1.f : 0.f);
            oB0[X] = make_float2((cgB[X] &  1u) ? 1.f : 0.f, (cgB[X] &  8u) ? 1.f : 0.f);
            oB1[X] = make_float2((cgB[X] &  2u) ? 1.f : 0.f, (cgB[X] & 16u) ? 1.f : 0.f);
            oB2[X] = make_float2((cgB[X] &  4u) ? 1.f : 0.f, (cgB[X] & 32u) ? 1.f : 0.f);

            float2* D = smf2 + X * SBAT2 + base2;   // buffer 0
            D[0]               = oA0[X];
            D[PLANE2]          = oA1[X];
            D[2 * PLANE2]      = oA2[X];
            D[PEC]             = oB0[X];
            D[PLANE2 + PEC]    = oB1[X];
            D[2 * PLANE2 + PEC]= oB2[X];
        }
    }
    __syncthreads();

    const int iters = n_iter[0];
    int spO2 = 0;

    for (int s = 0; s < iters; ++s) {
        if (active) {
            #pragma unroll
            for (int X = 0; X < NB; ++X) {
                const float2* S = smf2 + X * SBAT2 + spO2 + base2;
                float2*       D = smf2 + X * SBAT2 + (spO2 ^ NF2) + base2;

                // 10 plane loads per batch (independent across batches)
                float2 a0 = S[1];                        // P0, dir0
                float2 a3 = S[-1];                       // P0, dir3
                float2 a4 = S[PLANE2 - PEC];             // P1, dir4
                float2 a2 = S[2 * PLANE2 + PEC - 1];     // P2, dir2
                float2 a5 = S[2 * PLANE2 - PEC + 1];     // P2, dir5
                float2 b0 = S[PEC + 1];                  // P0, B dir0
                float2 b3 = S[PEC - 1];                  // P0, B dir3
                float2 b1 = S[PLANE2 + 2 * PEC];         // P1, B dir1
                float2 b2 = S[2 * PLANE2 + 2 * PEC - 1]; // P2, B dir2
                float2 b5 = S[2 * PLANE2 + 1];           // P2, B dir5

                float mA0 = fmaxf(fmaxf(a0.x, a3.x),  fmaxf(oA1[X].x, oA2[X].y));
                float mA1 = fmaxf(fmaxf(oB1[X].x, a4.x), fmaxf(oA2[X].x, oA0[X].x));
                float mA2 = fmaxf(fmaxf(a2.x, a5.x),  fmaxf(oA0[X].y, oA1[X].x));
                float mA3 = fmaxf(fmaxf(a3.y, a0.y),  fmaxf(oA1[X].y, oA2[X].x));
                float mA4 = fmaxf(fmaxf(a4.y, oB1[X].y), fmaxf(oA2[X].y, oA0[X].y));
                float mA5 = fmaxf(fmaxf(a5.y, a2.y),  fmaxf(oA0[X].x, oA1[X].y));

                float mB0 = fmaxf(fmaxf(b0.x, b3.x),  fmaxf(oB1[X].x, oB2[X].y));
                float mB1 = fmaxf(fmaxf(b1.x, oA1[X].x), fmaxf(oB2[X].x, oB0[X].x));
                float mB2 = fmaxf(fmaxf(b2.x, b5.x),  fmaxf(oB0[X].y, oB1[X].x));
                float mB3 = fmaxf(fmaxf(b3.y, b0.y),  fmaxf(oB1[X].y, oB2[X].x));
                float mB4 = fmaxf(fmaxf(oA1[X].y, b1.y), fmaxf(oB2[X].y, oB0[X].y));
                float mB5 = fmaxf(fmaxf(b5.y, b2.y),  fmaxf(oB0[X].x, oB1[X].y));

                oA0[X].x = fmaf(AmA[X], mA0, (cgA[X] &  1u) ? 1.f : 0.f);
                oA0[X].y = fmaf(AmA[X], mA3, (cgA[X] &  8u) ? 1.f : 0.f);
                oA1[X].x = fmaf(AmA[X], mA1, (cgA[X] &  2u) ? 1.f : 0.f);
                oA1[X].y = fmaf(AmA[X], mA4, (cgA[X] & 16u) ? 1.f : 0.f);
                oA2[X].x = fmaf(AmA[X], mA2, (cgA[X] &  4u) ? 1.f : 0.f);
                oA2[X].y = fmaf(AmA[X], mA5, (cgA[X] & 32u) ? 1.f : 0.f);
                oB0[X].x = fmaf(AmB[X], mB0, (cgB[X] &  1u) ? 1.f : 0.f);
                oB0[X].y = fmaf(AmB[X], mB3, (cgB[X] &  8u) ? 1.f : 0.f);
                oB1[X].x = fmaf(AmB[X], mB1, (cgB[X] &  2u) ? 1.f : 0.f);
                oB1[X].y = fmaf(AmB[X], mB4, (cgB[X] & 16u) ? 1.f : 0.f);
                oB2[X].x = fmaf(AmB[X], mB2, (cgB[X] &  4u) ? 1.f : 0.f);
                oB2[X].y = fmaf(AmB[X], mB5, (cgB[X] & 32u) ? 1.f : 0.f);

                D[0]                = oA0[X];
                D[PLANE2]           = oA1[X];
                D[2 * PLANE2]       = oA2[X];
                D[PEC]              = oB0[X];
                D[PLANE2 + PEC]     = oB1[X];
                D[2 * PLANE2 + PEC] = oB2[X];
            }
        }
        spO2 ^= NF2;
        __syncthreads();
    }
    // smf2 + X*SBAT2 + spO2 holds final s_plus planes for batch X

    if (tid < 4 * NB) {
        int X     = tid >> 2;
        int a     = tid & 3;
        int bb    = b0 + X;
        int alpha = state[bb * 3 + 0];
        int u     = state[bb * 3 + 1];
        int v     = state[bb * 3 + 2];
        int rot   = (alpha + 1) % 6;
        int uu    = u - (v >> 1) + ADDC;

        int p, ddr = 0, ddc = 0;
        int drr = (int)((DR_PACK >> (2 * rot)) & 3u) - 1;
        int dcc = (int)((DC_PACK >> (2 * rot)) & 3u) - 1;
        if (a == 0)      { p = rot; ddr =  drr; ddc =  dcc; }
        else if (a == 1) { p = rot; ddr = -drr; ddc = -dcc; }
        else if (a == 2) { p = (rot + 1) % 6; }
        else             { p = (rot + 5) % 6; }

        float q = 0.0f;
        if ((obsh[X * HH + uu] >> v) & 1u) {
            int f2idx = X * SBAT2 + spO2 + (p % 3) * PLANE2
                      + (uu + ddr + 1) * PEC + (v + ddc + 1);
            q = sm[2 * f2idx + (p >= 3 ? 1 : 0)];
        }
        out[bb * 4 + a] = q;
    }
}

extern "C" void kernel_launch(void* const* d_in, const int* in_sizes, int n_in,
                              void* d_out, int out_size) {
    const float* goals  = (const float*)d_in[0];
    const int*   state  = (const int*)  d_in[1];
    const float* obst   = (const float*)d_in[2];
    const int*   n_iter = (const int*)  d_in[3];
    float* out = (float*)d_out;

    cudaFuncSetAttribute(vin_kernel,
                         cudaFuncAttributeMaxDynamicSharedMemorySize, SMEM_BYTES);

    int B = out_size / 4;        // 512
    vin_kernel<<<B / NB, NTH, SMEM_BYTES>>>(goals, state, obst, n_iter, out);
}

// round 14
// speedup vs baseline: 1.0793x; 1.0793x over previous
#include <cuda_runtime.h>

#define EE 25
#define HH 37
#define NJ 6
#define PEC 30                  // padded cols (even), pc = c + 2
#define P0B 0                   // plane0: 38 rows (prow = r, 0..37)
#define P1B 1140                // plane1: 40 rows (prow = r+1, 0..39)
#define P2B 2340                // plane2: 40 rows (prow = r+1, 0..39)
#define NF2 3540                // f2 per buffer
#define NQ 13                   // quads per band (cols 0..25, col 25 dead)
#define NBANDS 19               // bands of 2 rows (rows 0..37, row 37 dead)
#define NACT (NQ * NBANDS)      // 247 active threads
#define NTH 256
#define GAMMA 0.9f
#define ADDC 12

// dr = {0,1,1,0,-1,-1} ; dc = {1,0,-1,-1,0,1}  packed (d+1), 2 bits per k
#define DR_PACK 105u
#define DC_PACK 2310u

#define SMEM_BYTES (2 * NF2 * 8)   // 56640 B -> 4 CTAs/SM

__device__ __forceinline__ float bf(unsigned m, int k) {
    return ((m >> k) & 1u) ? 1.0f : 0.0f;
}

__global__ __launch_bounds__(NTH, 4) void vin_kernel(
    const float* __restrict__ goals,   // [B,6,25,25]
    const int*   __restrict__ state,   // [B,3]
    const float* __restrict__ obst,    // [B,25,25]
    const int*   __restrict__ n_iter,  // [1]
    float* __restrict__ out)           // [B,4]
{
    extern __shared__ float2 smf2[];

    const int b   = blockIdx.x;
    const int tid = threadIdx.x;

    // ---- zero both buffers (7080 f2 = 3540 float4) ----
    {
        float4* z4 = (float4*)smf2;
        for (int i = tid; i < NF2; i += NTH)
            z4[i] = make_float4(0.f, 0.f, 0.f, 0.f);
    }
    __syncthreads();

    const bool active = (tid < NACT);
    int k0 = 0, k1 = 0, k2 = 0;
    float AmP = 0.f, AmQ = 0.f, AmR = 0.f, AmS = 0.f;
    unsigned cgq = 0u;   // P: bits 0-5, Q: 6-11, R: 12-17, S: 18-23
    float2 oP0, oP1, oP2, oQ0, oQ1, oQ2, oR0, oR1, oR2, oS0, oS1, oS2;
    oP0 = oP1 = oP2 = oQ0 = oQ1 = oQ2 = make_float2(0.f, 0.f);
    oR0 = oR1 = oR2 = oS0 = oS1 = oS2 = make_float2(0.f, 0.f);

    if (active) {
        int band = tid / NQ;
        int q    = tid - band * NQ;
        int rA = 2 * band, rB = rA + 1;
        int cL = 2 * q,    cR = cL + 1;
        k0 = P0B + rA * PEC + cL + 2;
        k1 = P1B + (rA + 1) * PEC + cL + 2;
        k2 = P2B + (rA + 1) * PEC + cL + 2;

        // per-cell masks straight from global
        int rr[2] = { rA, rB };
        int cc[2] = { cL, cR };
        float Amv[4];
        #pragma unroll
        for (int ri = 0; ri < 2; ++ri) {
            #pragma unroll
            for (int ci = 0; ci < 2; ++ci) {
                int cell = ri * 2 + ci;          // 0=P 1=Q 2=R 3=S
                int r = rr[ri], c = cc[ci];
                float Am = 0.f;
                unsigned g = 0u;
                if (r < HH && c < EE) {
                    int u = r + (c >> 1) - ADDC;
                    if (u >= 0 && u < EE) {
                        if (obst[(b * EE + u) * EE + c] == 0.0f) {
                            Am = GAMMA;
                            #pragma unroll
                            for (int j = 0; j < NJ; ++j)
                                if (goals[((b * NJ + j) * EE + u) * EE + c] != 0.0f)
                                    g |= (1u << j);
                        }
                    }
                }
                Amv[cell] = Am;
                int shift = (cell == 0) ? 0 : (cell == 1) ? 6 : (cell == 2) ? 12 : 18;
                cgq |= g << shift;
            }
        }
        AmP = Amv[0]; AmQ = Amv[1]; AmR = Amv[2]; AmS = Amv[3];

        // seed o = goal indicators (s_plus with val = 0)
        oP0 = make_float2(bf(cgq, 0),  bf(cgq, 3));
        oP1 = make_float2(bf(cgq, 1),  bf(cgq, 4));
        oP2 = make_float2(bf(cgq, 2),  bf(cgq, 5));
        oQ0 = make_float2(bf(cgq, 6),  bf(cgq, 9));
        oQ1 = make_float2(bf(cgq, 7),  bf(cgq, 10));
        oQ2 = make_float2(bf(cgq, 8),  bf(cgq, 11));
        oR0 = make_float2(bf(cgq, 12), bf(cgq, 15));
        oR1 = make_float2(bf(cgq, 13), bf(cgq, 16));
        oR2 = make_float2(bf(cgq, 14), bf(cgq, 17));
        oS0 = make_float2(bf(cgq, 18), bf(cgq, 21));
        oS1 = make_float2(bf(cgq, 19), bf(cgq, 22));
        oS2 = make_float2(bf(cgq, 20), bf(cgq, 23));

        float2* Db = smf2;   // buffer A
        *(float4*)(Db + k0)      = make_float4(oP0.x, oP0.y, oQ0.x, oQ0.y);
        *(float4*)(Db + k0 + 30) = make_float4(oR0.x, oR0.y, oS0.x, oS0.y);
        *(float4*)(Db + k1)      = make_float4(oP1.x, oP1.y, oQ1.x, oQ1.y);
        *(float4*)(Db + k1 + 30) = make_float4(oR1.x, oR1.y, oS1.x, oS1.y);
        *(float4*)(Db + k2)      = make_float4(oP2.x, oP2.y, oQ2.x, oQ2.y);
        *(float4*)(Db + k2 + 30) = make_float4(oR2.x, oR2.y, oS2.x, oS2.y);
    }
    __syncthreads();

    const int iters = n_iter[0];
    int spO2 = 0;

    for (int s = 0; s < iters; ++s) {
        if (active) {
            const float2* Sb = smf2 + spO2;
            float2*       Db = smf2 + (spO2 ^ NF2);

            // 12 loads (10 neighbors come from registers)
            float2 A  = Sb[k0 - 1];                  // P0 (rA, cL-1)   P.n3
            float2 Bx = Sb[k0 + 29];                 // P0 (rB, cL-1)   R.n3
            float2 C  = Sb[k0 + 2];                  // P0 (rA, cR+1)   Q.n0
            float2 D  = Sb[k0 + 32];                 // P0 (rB, cR+1)   S.n0
            float4 U4 = *(const float4*)(Sb + (k1 - 30));  // P1 (rA-1, cL..cR)  P.n4,Q.n4
            float4 N4 = *(const float4*)(Sb + (k1 + 60));  // P1 (rB+1, cL..cR)  R.n1,S.n1
            float2 E  = Sb[k2 + 29];                 // P2 (rB,   cL-1)  P.n2
            float2 F  = Sb[k2 + 59];                 // P2 (rB+1, cL-1)  R.n2
            float2 G  = Sb[k2 + 60];                 // P2 (rB+1, cL)    S.n2
            float2 Hh = Sb[k2 - 29];                 // P2 (rA-1, cR)    P.n5
            float2 I  = Sb[k2 - 28];                 // P2 (rA-1, cR+1)  Q.n5
            float2 J  = Sb[k2 + 2];                  // P2 (rA,   cR+1)  S.n5

            // P: n0=oQ0 n1=oR1 n2=E n3=A n4=U.lo n5=Hh
            float mP0 = fmaxf(fmaxf(oQ0.x, A.x),  fmaxf(oP1.x, oP2.y));
            float mP1 = fmaxf(fmaxf(oR1.x, U4.x), fmaxf(oP2.x, oP0.x));
            float mP2 = fmaxf(fmaxf(E.x,   Hh.x), fmaxf(oP0.y, oP1.x));
            float mP3 = fmaxf(fmaxf(A.y,   oQ0.y), fmaxf(oP1.y, oP2.x));
            float mP4 = fmaxf(fmaxf(U4.y,  oR1.y), fmaxf(oP2.y, oP0.y));
            float mP5 = fmaxf(fmaxf(Hh.y,  E.y),  fmaxf(oP0.x, oP1.y));

            // Q: n0=C n1=oS1 n2=oR2 n3=oP0 n4=U.hi n5=I
            float mQ0 = fmaxf(fmaxf(C.x,   oP0.x), fmaxf(oQ1.x, oQ2.y));
            float mQ1 = fmaxf(fmaxf(oS1.x, U4.z), fmaxf(oQ2.x, oQ0.x));
            float mQ2 = fmaxf(fmaxf(oR2.x, I.x),  fmaxf(oQ0.y, oQ1.x));
            float mQ3 = fmaxf(fmaxf(oP0.y, C.y),  fmaxf(oQ1.y, oQ2.x));
            float mQ4 = fmaxf(fmaxf(U4.w,  oS1.y), fmaxf(oQ2.y, oQ0.y));
            float mQ5 = fmaxf(fmaxf(I.y,   oR2.y), fmaxf(oQ0.x, oQ1.y));

            // R: n0=oS0 n1=N.lo n2=F n3=Bx n4=oP1 n5=oQ2
            float mR0 = fmaxf(fmaxf(oS0.x, Bx.x), fmaxf(oR1.x, oR2.y));
            float mR1 = fmaxf(fmaxf(N4.x,  oP1.x), fmaxf(oR2.x, oR0.x));
            float mR2 = fmaxf(fmaxf(F.x,   oQ2.x), fmaxf(oR0.y, oR1.x));
            float mR3 = fmaxf(fmaxf(Bx.y,  oS0.y), fmaxf(oR1.y, oR2.x));
            float mR4 = fmaxf(fmaxf(oP1.y, N4.y), fmaxf(oR2.y, oR0.y));
            float mR5 = fmaxf(fmaxf(oQ2.y, F.y),  fmaxf(oR0.x, oR1.y));

            // S: n0=D n1=N.hi n2=G n3=oR0 n4=oQ1 n5=J
            float mS0 = fmaxf(fmaxf(D.x,   oR0.x), fmaxf(oS1.x, oS2.y));
            float mS1 = fmaxf(fmaxf(N4.z,  oQ1.x), fmaxf(oS2.x, oS0.x));
            float mS2 = fmaxf(fmaxf(G.x,   J.x),  fmaxf(oS0.y, oS1.x));
            float mS3 = fmaxf(fmaxf(oR0.y, D.y),  fmaxf(oS1.y, oS2.x));
            float mS4 = fmaxf(fmaxf(oQ1.y, N4.w), fmaxf(oS2.y, oS0.y));
            float mS5 = fmaxf(fmaxf(J.y,   G.y),  fmaxf(oS0.x, oS1.y));

            oP0.x = fmaf(AmP, mP0, bf(cgq, 0));
            oP0.y = fmaf(AmP, mP3, bf(cgq, 3));
            oP1.x = fmaf(AmP, mP1, bf(cgq, 1));
            oP1.y = fmaf(AmP, mP4, bf(cgq, 4));
            oP2.x = fmaf(AmP, mP2, bf(cgq, 2));
            oP2.y = fmaf(AmP, mP5, bf(cgq, 5));
            oQ0.x = fmaf(AmQ, mQ0, bf(cgq, 6));
            oQ0.y = fmaf(AmQ, mQ3, bf(cgq, 9));
            oQ1.x = fmaf(AmQ, mQ1, bf(cgq, 7));
            oQ1.y = fmaf(AmQ, mQ4, bf(cgq, 10));
            oQ2.x = fmaf(AmQ, mQ2, bf(cgq, 8));
            oQ2.y = fmaf(AmQ, mQ5, bf(cgq, 11));
            oR0.x = fmaf(AmR, mR0, bf(cgq, 12));
            oR0.y = fmaf(AmR, mR3, bf(cgq, 15));
            oR1.x = fmaf(AmR, mR1, bf(cgq, 13));
            oR1.y = fmaf(AmR, mR4, bf(cgq, 16));
            oR2.x = fmaf(AmR, mR2, bf(cgq, 14));
            oR2.y = fmaf(AmR, mR5, bf(cgq, 17));
            oS0.x = fmaf(AmS, mS0, bf(cgq, 18));
            oS0.y = fmaf(AmS, mS3, bf(cgq, 21));
            oS1.x = fmaf(AmS, mS1, bf(cgq, 19));
            oS1.y = fmaf(AmS, mS4, bf(cgq, 22));
            oS2.x = fmaf(AmS, mS2, bf(cgq, 20));
            oS2.y = fmaf(AmS, mS5, bf(cgq, 23));

            *(float4*)(Db + k0)      = make_float4(oP0.x, oP0.y, oQ0.x, oQ0.y);
            *(float4*)(Db + k0 + 30) = make_float4(oR0.x, oR0.y, oS0.x, oS0.y);
            *(float4*)(Db + k1)      = make_float4(oP1.x, oP1.y, oQ1.x, oQ1.y);
            *(float4*)(Db + k1 + 30) = make_float4(oR1.x, oR1.y, oS1.x, oS1.y);
            *(float4*)(Db + k2)      = make_float4(oP2.x, oP2.y, oQ2.x, oQ2.y);
            *(float4*)(Db + k2 + 30) = make_float4(oR2.x, oR2.y, oS2.x, oS2.y);
        }
        spO2 ^= NF2;
        __syncthreads();
    }
    // final s_plus in buffer at offset spO2

    if (tid < 4) {
        int a     = tid;
        int alpha = state[b * 3 + 0];
        int u     = state[b * 3 + 1];
        int v     = state[b * 3 + 2];
        int rot   = (alpha + 1) % 6;
        int uu    = u - (v >> 1) + ADDC;

        int p, ddr = 0, ddc = 0;
        int drr = (int)((DR_PACK >> (2 * rot)) & 3u) - 1;
        int dcc = (int)((DC_PACK >> (2 * rot)) & 3u) - 1;
        if (a == 0)      { p = rot; ddr =  drr; ddc =  dcc; }
        else if (a == 1) { p = rot; ddr = -drr; ddc = -dcc; }
        else if (a == 2) { p = (rot + 1) % 6; }
        else             { p = (rot + 5) % 6; }

        float qv = 0.0f;
        if (obst[(b * EE + u) * EE + v] == 0.0f) {
            int pm   = p % 3;
            // plane0 (pm==0) has ddr==0 always (dirs 0/3 are horizontal)
            int base = (pm == 0) ? P0B : ((pm == 1) ? P1B : P2B);
            int prow = (pm == 0) ? uu : (uu + ddr + 1);
            float2 val = smf2[spO2 + base + prow * PEC + (v + ddc + 2)];
            qv = (p < 3) ? val.x : val.y;
        }
        out[b * 4 + a] = qv;
    }
}

extern "C" void kernel_launch(void* const* d_in, const int* in_sizes, int n_in,
                              void* d_out, int out_size) {
    const float* goals  = (const float*)d_in[0];
    const int*   state  = (const int*)  d_in[1];
    const float* obst   = (const float*)d_in[2];
    const int*   n_iter = (const int*)  d_in[3];
    float* out = (float*)d_out;

    cudaFuncSetAttribute(vin_kernel,
                         cudaFuncAttributeMaxDynamicSharedMemorySize, SMEM_BYTES);

    int B = out_size / 4;   // 512
    vin_kernel<<<B, NTH, SMEM_BYTES>>>(goals, state, obst, n_iter, out);
}